// round 2
// baseline (speedup 1.0000x reference)
#include <cuda_runtime.h>
#include <math.h>

#define BB    128
#define SEQ   64
#define CH    256
#define PARTS 16
#define HID   64

#define XS_STRIDE 68    // x slice rows padded: cols 0,1 and 66,67 are zero
#define HB_STRIDE 66    // h rows padded: cols 0 and 65 are zero
#define AS_STRIDE 130   // phase1 weight tile [kk][r], even stride
#define A_STRIDE  66    // phase2 weight tiles [kk][c_local]

// dynamic smem layout (floats):
//   xs : CH * XS_STRIDE          = 17408
//   hb : 128 * HB_STRIDE         =  8448
//   wb : max(96*130, 256*66)     = 16896
#define SMEM_FLOATS (CH*XS_STRIDE + 128*HB_STRIDE + 16896)

__device__ __forceinline__ float sigmoidf_fast(float v) {
    return 1.0f / (1.0f + __expf(-v));
}

__global__ void __launch_bounds__(256, 1)
mtb_kernel(const float* __restrict__ x,
           const float* __restrict__ W1a,
           const float* __restrict__ W1b,
           const float* __restrict__ W2a,
           const float* __restrict__ W2b,
           float* __restrict__ out)
{
    extern __shared__ float smem[];
    float* xs = smem;                        // [256][68]
    float* hb = xs + CH * XS_STRIDE;         // [128][66]  rows 0..63 = h1, 64..127 = h2
    float* wb = hb + 128 * HB_STRIDE;        // weight staging

    const int tid = threadIdx.x;
    const int b   = blockIdx.x >> 4;
    const int p   = blockIdx.x & 15;
    const int ty  = tid >> 4;    // 0..15
    const int tx  = tid & 15;    // 0..15

    // ---- zero pads ----
    {
        float* row = xs + tid * XS_STRIDE;   // one row per thread (256 rows)
        row[0] = 0.f; row[1] = 0.f; row[66] = 0.f; row[67] = 0.f;
    }
    if (tid < 128) {
        float* row = hb + tid * HB_STRIDE;
        row[0] = 0.f; row[65] = 0.f;
    }

    // ---- load x slice: xf[c][s] = x[((b*64+s)*256+c)*16+p], data at col s+2 ----
    {
        const float* xb = x + (size_t)b * (SEQ * CH * PARTS) + p;
        float* xrow = xs + tid * XS_STRIDE + 2;      // c = tid
        #pragma unroll 8
        for (int s = 0; s < SEQ; s++) {
            xrow[s] = xb[(size_t)(s * CH + tid) * PARTS];
        }
    }

    // ================= Phase 1: h1|h2 = leaky(conv3(xf, W{1,2}a)) =================
    // C[r=0..127][s=0..63], K = 768 over (c,k). r<64 -> W1a, r>=64 -> W2a.
    float acc[8][4];
    #pragma unroll
    for (int i = 0; i < 8; i++)
        #pragma unroll
        for (int j = 0; j < 4; j++) acc[i][j] = 0.f;

    const float* Wa1 = W1a + (size_t)p * (HID * CH * 3);   // viewed as [64][768]
    const float* Wa2 = W2a + (size_t)p * (HID * CH * 3);

    for (int c0 = 0; c0 < CH; c0 += 32) {
        __syncthreads();
        // stage As[kk][r] for kk = cl*3+k (cl in 0..31), r in 0..127
        #pragma unroll 4
        for (int i = tid; i < 96 * 128; i += 256) {
            int r  = i / 96;
            int kk = i - r * 96;
            float v = (r < 64) ? Wa1[r * 768 + c0 * 3 + kk]
                               : Wa2[(r - 64) * 768 + c0 * 3 + kk];
            wb[kk * AS_STRIDE + r] = v;
        }
        __syncthreads();

        #pragma unroll 2
        for (int cl = 0; cl < 32; cl++) {
            const float* xrow = xs + (c0 + cl) * XS_STRIDE + tx + 1;
            float bv[4][3];
            #pragma unroll
            for (int j = 0; j < 4; j++) {
                bv[j][0] = xrow[16 * j + 0];
                bv[j][1] = xrow[16 * j + 1];
                bv[j][2] = xrow[16 * j + 2];
            }
            #pragma unroll
            for (int k = 0; k < 3; k++) {
                const float* arow = wb + (cl * 3 + k) * AS_STRIDE + ty * 8;
                float av[8];
                #pragma unroll
                for (int i = 0; i < 8; i++) av[i] = arow[i];
                #pragma unroll
                for (int i = 0; i < 8; i++)
                    #pragma unroll
                    for (int j = 0; j < 4; j++)
                        acc[i][j] = fmaf(av[i], bv[j][k], acc[i][j]);
            }
        }
    }

    // leaky relu epilogue -> hb (data col s+1)
    #pragma unroll
    for (int i = 0; i < 8; i++) {
        float* hrow = hb + (ty * 8 + i) * HB_STRIDE + 1;
        #pragma unroll
        for (int j = 0; j < 4; j++) {
            float v = acc[i][j];
            hrow[tx + 16 * j] = (v > 0.f) ? v : 0.01f * v;
        }
    }

    // ================= Phase 2: logits + pools + gates + temporal max ============
    const float* Wb1 = W1b + (size_t)p * (CH * HID);       // [256][64]
    const float* Wb2 = W2b + (size_t)p * (CH * HID * 3);   // [256][192]
    float* A1s = wb;                    // [64][66]
    float* A2s = wb + 64 * A_STRIDE;    // [192][66]

    for (int c0 = 0; c0 < CH; c0 += 64) {
        __syncthreads();
        // stage A1s[h][cl]
        #pragma unroll 4
        for (int i = tid; i < 64 * 64; i += 256) {
            int cl = i >> 6, h = i & 63;
            A1s[h * A_STRIDE + cl] = Wb1[(c0 + cl) * 64 + h];
        }
        // stage A2s[h*3+k][cl]
        #pragma unroll 4
        for (int i = tid; i < 64 * 192; i += 256) {
            int cl = i / 192, kk = i - cl * 192;
            A2s[kk * A_STRIDE + cl] = Wb2[(c0 + cl) * 192 + kk];
        }
        __syncthreads();

        float a1c[4][4], a2c[4][4];
        #pragma unroll
        for (int i = 0; i < 4; i++)
            #pragma unroll
            for (int j = 0; j < 4; j++) { a1c[i][j] = 0.f; a2c[i][j] = 0.f; }

        // branch 1: logits1[c][s] = sum_h W1b[c][h] * h1[h][s]  (K = 64)
        #pragma unroll 4
        for (int kk = 0; kk < 64; kk++) {
            const float* arow = A1s + kk * A_STRIDE + ty * 4;
            const float* brow = hb + kk * HB_STRIDE + tx + 1;
            float av[4], bv[4];
            #pragma unroll
            for (int i = 0; i < 4; i++) av[i] = arow[i];
            #pragma unroll
            for (int j = 0; j < 4; j++) bv[j] = brow[16 * j];
            #pragma unroll
            for (int i = 0; i < 4; i++)
                #pragma unroll
                for (int j = 0; j < 4; j++)
                    a1c[i][j] = fmaf(av[i], bv[j], a1c[i][j]);
        }

        // branch 2: logits2[c][s] = sum_{h,k} W2b[c][h][k] * h2[h][s+k-1]  (K = 192)
        #pragma unroll 2
        for (int hl = 0; hl < 64; hl++) {
            const float* brow = hb + (64 + hl) * HB_STRIDE + tx;
            float bv[4][3];
            #pragma unroll
            for (int j = 0; j < 4; j++) {
                bv[j][0] = brow[16 * j + 0];
                bv[j][1] = brow[16 * j + 1];
                bv[j][2] = brow[16 * j + 2];
            }
            #pragma unroll
            for (int k = 0; k < 3; k++) {
                const float* arow = A2s + (hl * 3 + k) * A_STRIDE + ty * 4;
                float av[4];
                #pragma unroll
                for (int i = 0; i < 4; i++) av[i] = arow[i];
                #pragma unroll
                for (int i = 0; i < 4; i++)
                    #pragma unroll
                    for (int j = 0; j < 4; j++)
                        a2c[i][j] = fmaf(av[i], bv[j][k], a2c[i][j]);
            }
        }

        // epilogue: pools + sigmoid gates + combine + max over s
        #pragma unroll
        for (int i = 0; i < 4; i++) {
            const float* xrow = xs + (c0 + ty * 4 + i) * XS_STRIDE;
            float m = -INFINITY;
            #pragma unroll
            for (int j = 0; j < 4; j++) {
                int s = tx + 16 * j;
                // data col = s+2; avg3 window cols s+1..s+3; avg5 window cols s..s+4
                float x0 = xrow[s + 0], x1 = xrow[s + 1], x2 = xrow[s + 2];
                float x3 = xrow[s + 3], x4 = xrow[s + 4];
                float avg3 = (x1 + x2 + x3) * (1.0f / 3.0f);
                float avg5 = (x0 + x1 + x2 + x3 + x4) * 0.2f;
                // max pools pad with -inf: include neighbors only when in-range
                float mx3 = x2;
                if (s >= 1)  mx3 = fmaxf(mx3, x1);
                if (s <= 62) mx3 = fmaxf(mx3, x3);
                float mx5 = mx3;
                if (s >= 2)  mx5 = fmaxf(mx5, x0);
                if (s <= 61) mx5 = fmaxf(mx5, x4);

                float g1 = sigmoidf_fast(a1c[i][j]);
                float g2 = sigmoidf_fast(a2c[i][j]);
                float val = (avg3 + mx3) * g1 + (avg5 + mx5) * g2;
                m = fmaxf(m, val);
            }
            // max-reduce across the 16 tx lanes (stays within half-warp)
            #pragma unroll
            for (int off = 8; off > 0; off >>= 1)
                m = fmaxf(m, __shfl_xor_sync(0xffffffffu, m, off));
            if (tx == 0)
                out[(size_t)blockIdx.x * CH + c0 + ty * 4 + i] = m;
        }
    }
}

extern "C" void kernel_launch(void* const* d_in, const int* in_sizes, int n_in,
                              void* d_out, int out_size)
{
    const float* x   = (const float*)d_in[0];
    const float* W1a = (const float*)d_in[1];
    const float* W1b = (const float*)d_in[2];
    const float* W2a = (const float*)d_in[3];
    const float* W2b = (const float*)d_in[4];
    float* out = (float*)d_out;

    const int smem_bytes = SMEM_FLOATS * (int)sizeof(float);   // 171008
    cudaFuncSetAttribute(mtb_kernel, cudaFuncAttributeMaxDynamicSharedMemorySize,
                         smem_bytes);
    mtb_kernel<<<BB * PARTS, 256, smem_bytes>>>(x, W1a, W1b, W2a, W2b, out);
}

// round 3
// speedup vs baseline: 1.1001x; 1.1001x over previous
#include <cuda_runtime.h>
#include <math.h>

#define BB    128
#define SEQ   64
#define CH    256
#define PARTS 16
#define HID   64
#define NTHREADS 512

#define XS_STRIDE 68    // x slice rows padded: cols 0,1 and 66,67 are zero
#define HB_STRIDE 66    // h rows padded: cols 0 and 65 are zero
#define AS_STRIDE 130   // phase1 weight tile [kk][r], even stride
#define A_STRIDE  66    // phase2 weight tiles [kk][c_local]

// dynamic smem layout (floats):
//   xs : CH * XS_STRIDE          = 17408
//   hb : 128 * HB_STRIDE         =  8448
//   wb : max(96*130, 256*66)     = 16896
#define SMEM_FLOATS (CH*XS_STRIDE + 128*HB_STRIDE + 16896)

typedef unsigned long long u64;

__device__ __forceinline__ u64 packrep(float a) {
    u64 r; asm("mov.b64 %0, {%1, %1};" : "=l"(r) : "f"(a)); return r;
}
__device__ __forceinline__ void unpack2(u64 v, float& lo, float& hi) {
    asm("mov.b64 {%0, %1}, %2;" : "=f"(lo), "=f"(hi) : "l"(v));
}
__device__ __forceinline__ u64 ffma2(u64 a, u64 b, u64 c) {
    u64 d; asm("fma.rn.f32x2 %0, %1, %2, %3;" : "=l"(d) : "l"(a), "l"(b), "l"(c));
    return d;
}
__device__ __forceinline__ u64 lds64(const float* p) {
    return *reinterpret_cast<const u64*>(p);   // p is 8B-aligned by construction
}
__device__ __forceinline__ float sigmoidf_fast(float v) {
    return 1.0f / (1.0f + __expf(-v));
}
__device__ __forceinline__ float leaky(float v) {
    return (v > 0.f) ? v : 0.01f * v;
}

__global__ void __launch_bounds__(NTHREADS, 1)
mtb_kernel(const float* __restrict__ x,
           const float* __restrict__ W1a,
           const float* __restrict__ W1b,
           const float* __restrict__ W2a,
           const float* __restrict__ W2b,
           float* __restrict__ out)
{
    extern __shared__ float smem[];
    float* xs = smem;                        // [256][68]
    float* hb = xs + CH * XS_STRIDE;         // [128][66]  rows 0..63 = h1, 64..127 = h2
    float* wb = hb + 128 * HB_STRIDE;        // weight staging

    const int tid = threadIdx.x;
    const int b   = blockIdx.x >> 4;
    const int p   = blockIdx.x & 15;

    // ---- zero pads ----
    if (tid < 256) {
        float* row = xs + tid * XS_STRIDE;
        row[0] = 0.f; row[1] = 0.f; row[66] = 0.f; row[67] = 0.f;
    }
    if (tid < 128) {
        float* row = hb + tid * HB_STRIDE;
        row[0] = 0.f; row[65] = 0.f;
    }

    // ---- load x slice: xf[c][s] = x[((b*64+s)*256+c)*16+p], data at col s+2 ----
    {
        const int c  = tid & 255;
        const int sh = tid >> 8;          // 0 or 1 -> s halves
        const float* xb = x + (size_t)b * (SEQ * CH * PARTS) + p;
        float* xrow = xs + c * XS_STRIDE + 2 + sh * 32;
        #pragma unroll 8
        for (int s = 0; s < 32; s++) {
            xrow[s] = xb[(size_t)((sh * 32 + s) * CH + c) * PARTS];
        }
    }

    // ================= Phase 1: h1|h2 = leaky(conv3(xf, W{1,2}a)) =================
    // C[r=0..127][s=0..63], K = 768 over (c,k). r<64 -> W1a, r>=64 -> W2a.
    // 512 threads: ty1 in 0..31 owns rows ty1*4..+3 (2 row-pairs), tx1 in 0..15
    // owns cols tx1 + 16*j, j=0..3. Row-pairs packed as f32x2.
    const int ty1 = tid >> 4;    // 0..31
    const int tx1 = tid & 15;    // 0..15

    u64 acc2[2][4];
    #pragma unroll
    for (int u = 0; u < 2; u++)
        #pragma unroll
        for (int j = 0; j < 4; j++) acc2[u][j] = 0ull;

    const float* Wa1 = W1a + (size_t)p * (HID * CH * 3);   // viewed as [64][768]
    const float* Wa2 = W2a + (size_t)p * (HID * CH * 3);

    for (int c0 = 0; c0 < CH; c0 += 32) {
        __syncthreads();
        // stage As[kk][r] for kk = cl*3+k (cl in 0..31), r in 0..127
        #pragma unroll 4
        for (int i = tid; i < 96 * 128; i += NTHREADS) {
            int r  = i / 96;
            int kk = i - r * 96;
            float v = (r < 64) ? Wa1[r * 768 + c0 * 3 + kk]
                               : Wa2[(r - 64) * 768 + c0 * 3 + kk];
            wb[kk * AS_STRIDE + r] = v;
        }
        __syncthreads();

        #pragma unroll 2
        for (int cl = 0; cl < 32; cl++) {
            const float* xrow = xs + (c0 + cl) * XS_STRIDE + tx1 + 1;
            u64 bvp[3][4];
            #pragma unroll
            for (int j = 0; j < 4; j++) {
                bvp[0][j] = packrep(xrow[16 * j + 0]);
                bvp[1][j] = packrep(xrow[16 * j + 1]);
                bvp[2][j] = packrep(xrow[16 * j + 2]);
            }
            #pragma unroll
            for (int k = 0; k < 3; k++) {
                const float* arow = wb + (cl * 3 + k) * AS_STRIDE + ty1 * 4;
                u64 av0 = lds64(arow);
                u64 av1 = lds64(arow + 2);
                #pragma unroll
                for (int j = 0; j < 4; j++) {
                    acc2[0][j] = ffma2(av0, bvp[k][j], acc2[0][j]);
                    acc2[1][j] = ffma2(av1, bvp[k][j], acc2[1][j]);
                }
            }
        }
    }

    // leaky relu epilogue -> hb (data col s+1)
    #pragma unroll
    for (int u = 0; u < 2; u++) {
        float* hrow0 = hb + (ty1 * 4 + 2 * u)     * HB_STRIDE + 1 + tx1;
        float* hrow1 = hb + (ty1 * 4 + 2 * u + 1) * HB_STRIDE + 1 + tx1;
        #pragma unroll
        for (int j = 0; j < 4; j++) {
            float lo, hi; unpack2(acc2[u][j], lo, hi);
            hrow0[16 * j] = leaky(lo);
            hrow1[16 * j] = leaky(hi);
        }
    }

    // ================= Phase 2: logits + pools + gates + temporal max ============
    // 512 threads: ty2 in 0..15 owns c-rows ty2*4..+3 (2 row-pairs),
    // tx2 in 0..31 owns cols tx2 + 32*j, j=0..1. Whole warp shares ty2.
    const int ty2 = tid >> 5;    // 0..15
    const int tx2 = tid & 31;    // 0..31

    const float* Wb1 = W1b + (size_t)p * (CH * HID);       // [256][64]
    const float* Wb2 = W2b + (size_t)p * (CH * HID * 3);   // [256][192]
    float* A1s = wb;                    // [64][66]
    float* A2s = wb + 64 * A_STRIDE;    // [192][66]

    for (int c0 = 0; c0 < CH; c0 += 64) {
        __syncthreads();   // hb writes visible; phase1/prev-chunk wb reads done
        // stage A1s[h][cl]
        #pragma unroll 2
        for (int i = tid; i < 64 * 64; i += NTHREADS) {
            int cl = i >> 6, h = i & 63;
            A1s[h * A_STRIDE + cl] = Wb1[(c0 + cl) * 64 + h];
        }
        // stage A2s[h*3+k][cl]
        #pragma unroll 4
        for (int i = tid; i < 64 * 192; i += NTHREADS) {
            int cl = i / 192, kk = i - cl * 192;
            A2s[kk * A_STRIDE + cl] = Wb2[(c0 + cl) * 192 + kk];
        }
        __syncthreads();

        u64 a1c2[2][2], a2c2[2][2];
        #pragma unroll
        for (int u = 0; u < 2; u++)
            #pragma unroll
            for (int j = 0; j < 2; j++) { a1c2[u][j] = 0ull; a2c2[u][j] = 0ull; }

        // branch 1: logits1[c][s] = sum_h W1b[c][h] * h1[h][s]  (K = 64)
        #pragma unroll 4
        for (int kk = 0; kk < 64; kk++) {
            const float* arow = A1s + kk * A_STRIDE + ty2 * 4;
            const float* brow = hb + kk * HB_STRIDE + tx2 + 1;
            u64 av0 = lds64(arow);
            u64 av1 = lds64(arow + 2);
            u64 bv0 = packrep(brow[0]);
            u64 bv1 = packrep(brow[32]);
            a1c2[0][0] = ffma2(av0, bv0, a1c2[0][0]);
            a1c2[1][0] = ffma2(av1, bv0, a1c2[1][0]);
            a1c2[0][1] = ffma2(av0, bv1, a1c2[0][1]);
            a1c2[1][1] = ffma2(av1, bv1, a1c2[1][1]);
        }

        // branch 2: logits2[c][s] = sum_{h,k} W2b[c][h][k] * h2[h][s+k-1]  (K = 192)
        #pragma unroll 2
        for (int hl = 0; hl < 64; hl++) {
            const float* brow = hb + (64 + hl) * HB_STRIDE + tx2;
            u64 bvp[3][2];
            #pragma unroll
            for (int k = 0; k < 3; k++) {
                bvp[k][0] = packrep(brow[k]);
                bvp[k][1] = packrep(brow[32 + k]);
            }
            #pragma unroll
            for (int k = 0; k < 3; k++) {
                const float* arow = A2s + (hl * 3 + k) * A_STRIDE + ty2 * 4;
                u64 av0 = lds64(arow);
                u64 av1 = lds64(arow + 2);
                #pragma unroll
                for (int j = 0; j < 2; j++) {
                    a2c2[0][j] = ffma2(av0, bvp[k][j], a2c2[0][j]);
                    a2c2[1][j] = ffma2(av1, bvp[k][j], a2c2[1][j]);
                }
            }
        }

        // unpack logits: l1[i][j], l2[i][j] with i = 2u + lane
        float l1[4][2], l2[4][2];
        #pragma unroll
        for (int u = 0; u < 2; u++)
            #pragma unroll
            for (int j = 0; j < 2; j++) {
                float lo, hi;
                unpack2(a1c2[u][j], lo, hi); l1[2*u][j] = lo; l1[2*u+1][j] = hi;
                unpack2(a2c2[u][j], lo, hi); l2[2*u][j] = lo; l2[2*u+1][j] = hi;
            }

        // epilogue: pools + sigmoid gates + combine + max over s
        #pragma unroll
        for (int i = 0; i < 4; i++) {
            const float* xrow = xs + (c0 + ty2 * 4 + i) * XS_STRIDE;
            float m = -INFINITY;
            #pragma unroll
            for (int j = 0; j < 2; j++) {
                int s = tx2 + 32 * j;
                // data col = s+2; avg3 window cols s+1..s+3; avg5 window cols s..s+4
                float x0 = xrow[s + 0], x1 = xrow[s + 1], x2 = xrow[s + 2];
                float x3 = xrow[s + 3], x4 = xrow[s + 4];
                float avg3 = (x1 + x2 + x3) * (1.0f / 3.0f);
                float avg5 = (x0 + x1 + x2 + x3 + x4) * 0.2f;
                float mx3 = x2;
                if (s >= 1)  mx3 = fmaxf(mx3, x1);
                if (s <= 62) mx3 = fmaxf(mx3, x3);
                float mx5 = mx3;
                if (s >= 2)  mx5 = fmaxf(mx5, x0);
                if (s <= 61) mx5 = fmaxf(mx5, x4);

                float g1 = sigmoidf_fast(l1[i][j]);
                float g2 = sigmoidf_fast(l2[i][j]);
                float val = (avg3 + mx3) * g1 + (avg5 + mx5) * g2;
                m = fmaxf(m, val);
            }
            // full-warp max reduce over the 32 s-lanes
            #pragma unroll
            for (int off = 16; off > 0; off >>= 1)
                m = fmaxf(m, __shfl_xor_sync(0xffffffffu, m, off));
            if (tx2 == 0)
                out[(size_t)blockIdx.x * CH + c0 + ty2 * 4 + i] = m;
        }
    }
}

extern "C" void kernel_launch(void* const* d_in, const int* in_sizes, int n_in,
                              void* d_out, int out_size)
{
    const float* x   = (const float*)d_in[0];
    const float* W1a = (const float*)d_in[1];
    const float* W1b = (const float*)d_in[2];
    const float* W2a = (const float*)d_in[3];
    const float* W2b = (const float*)d_in[4];
    float* out = (float*)d_out;

    const int smem_bytes = SMEM_FLOATS * (int)sizeof(float);   // 171008
    cudaFuncSetAttribute(mtb_kernel, cudaFuncAttributeMaxDynamicSharedMemorySize,
                         smem_bytes);
    mtb_kernel<<<BB * PARTS, NTHREADS, smem_bytes>>>(x, W1a, W1b, W2a, W2b, out);
}

// round 4
// speedup vs baseline: 1.1492x; 1.0446x over previous
#include <cuda_runtime.h>
#include <math.h>

#define BB    128
#define SEQ   64
#define CH    256
#define PARTS 16
#define HID   64
#define NTHREADS 512

#define XS_STRIDE 68    // x rows: data at col s+2; cols 0,1,66,67 zero
#define HB_STRIDE 68    // h rows: data at col s+2; cols 0,1,66,67 zero
#define AS_STRIDE 132   // phase1 weight tile [kk][r], 16B-aligned rows
#define A_STRIDE  68    // phase2 weight tiles [kk][c_local], 16B-aligned rows

#define WB_FLOATS (256*A_STRIDE)   // 17408 >= 96*AS_STRIDE (12672)
#define SMEM_FLOATS (CH*XS_STRIDE + 128*HB_STRIDE + WB_FLOATS)

typedef unsigned long long u64;

__device__ __forceinline__ u64 packrep(float a) {
    u64 r; asm("mov.b64 %0, {%1, %1};" : "=l"(r) : "f"(a)); return r;
}
__device__ __forceinline__ void unpack2(u64 v, float& lo, float& hi) {
    asm("mov.b64 {%0, %1}, %2;" : "=f"(lo), "=f"(hi) : "l"(v));
}
__device__ __forceinline__ u64 ffma2(u64 a, u64 b, u64 c) {
    u64 d; asm("fma.rn.f32x2 %0, %1, %2, %3;" : "=l"(d) : "l"(a), "l"(b), "l"(c));
    return d;
}
__device__ __forceinline__ u64 lds64(const float* p) {
    return *reinterpret_cast<const u64*>(p);
}
// 16B vector load -> two packed f32x2 operands
__device__ __forceinline__ void lds128p(const float* p, u64& a, u64& b) {
    ulonglong2 v = *reinterpret_cast<const ulonglong2*>(p);
    a = v.x; b = v.y;
}
__device__ __forceinline__ float sigmoidf_fast(float v) {
    return 1.0f / (1.0f + __expf(-v));
}
__device__ __forceinline__ float leaky(float v) {
    return (v > 0.f) ? v : 0.01f * v;
}

__global__ void __launch_bounds__(NTHREADS, 1)
mtb_kernel(const float* __restrict__ x,
           const float* __restrict__ W1a,
           const float* __restrict__ W1b,
           const float* __restrict__ W2a,
           const float* __restrict__ W2b,
           float* __restrict__ out)
{
    extern __shared__ float smem[];
    float* xs = smem;                        // [256][68]
    float* hb = xs + CH * XS_STRIDE;         // [128][68] rows 0..63 h1, 64..127 h2
    float* wb = hb + 128 * HB_STRIDE;        // weight staging

    const int tid = threadIdx.x;
    const int b   = blockIdx.x >> 4;
    const int p   = blockIdx.x & 15;

    // ---- zero pads ----
    if (tid < 256) {
        float* row = xs + tid * XS_STRIDE;
        row[0] = 0.f; row[1] = 0.f; row[66] = 0.f; row[67] = 0.f;
    }
    if (tid < 128) {
        float* row = hb + tid * HB_STRIDE;
        row[0] = 0.f; row[1] = 0.f; row[66] = 0.f; row[67] = 0.f;
    }

    // ---- load x slice: data col = s+2 ----
    {
        const int c  = tid & 255;
        const int sh = tid >> 8;          // 0/1 -> s halves
        const float* xb = x + (size_t)b * (SEQ * CH * PARTS) + p;
        float* xrow = xs + c * XS_STRIDE + 2 + sh * 32;
        #pragma unroll 8
        for (int s = 0; s < 32; s++) {
            xrow[s] = xb[(size_t)((sh * 32 + s) * CH + c) * PARTS];
        }
    }

    // ================= Phase 1: h1|h2 = leaky(conv3(xf, W{1,2}a)) =================
    // rows: ty1*4..+3 (2 row-pairs, f32x2 over rows). cols: s0=4*tx1 .. +3.
    const int ty1 = tid >> 4;    // 0..31
    const int tx1 = tid & 15;    // 0..15
    const int s0  = tx1 * 4;

    u64 acc2[2][4];
    #pragma unroll
    for (int u = 0; u < 2; u++)
        #pragma unroll
        for (int j = 0; j < 4; j++) acc2[u][j] = 0ull;

    const float* Wa1 = W1a + (size_t)p * (HID * CH * 3);   // [64][768]
    const float* Wa2 = W2a + (size_t)p * (HID * CH * 3);

    for (int c0 = 0; c0 < CH; c0 += 32) {
        __syncthreads();
        // stage As[kk][r], kk = cl*3+k (0..95), r 0..127
        #pragma unroll 4
        for (int i = tid; i < 96 * 128; i += NTHREADS) {
            int r  = i / 96;
            int kk = i - r * 96;
            float v = (r < 64) ? Wa1[r * 768 + c0 * 3 + kk]
                               : Wa2[(r - 64) * 768 + c0 * 3 + kk];
            wb[kk * AS_STRIDE + r] = v;
        }
        __syncthreads();

        const float* xq = xs + c0 * XS_STRIDE + s0;
        const float* aq = wb + ty1 * 4;
        #pragma unroll 4
        for (int cl = 0; cl < 32; cl++) {
            // x window: cols s0..s0+7, need x1..x6
            const float4 q0 = *reinterpret_cast<const float4*>(xq);
            const float4 q1 = *reinterpret_cast<const float4*>(xq + 4);
            u64 bp1 = packrep(q0.y), bp2 = packrep(q0.z), bp3 = packrep(q0.w);
            u64 bp4 = packrep(q1.x), bp5 = packrep(q1.y), bp6 = packrep(q1.z);
            u64 bp[7];
            bp[1]=bp1; bp[2]=bp2; bp[3]=bp3; bp[4]=bp4; bp[5]=bp5; bp[6]=bp6;
            #pragma unroll
            for (int k = 0; k < 3; k++) {
                u64 av0, av1;
                lds128p(aq + k * AS_STRIDE, av0, av1);
                #pragma unroll
                for (int j = 0; j < 4; j++) {
                    acc2[0][j] = ffma2(av0, bp[j + k + 1], acc2[0][j]);
                    acc2[1][j] = ffma2(av1, bp[j + k + 1], acc2[1][j]);
                }
            }
            xq += XS_STRIDE;
            aq += 3 * AS_STRIDE;
        }
    }

    // leaky relu -> hb (data col s+2)
    #pragma unroll
    for (int u = 0; u < 2; u++) {
        float* hrow0 = hb + (ty1 * 4 + 2 * u)     * HB_STRIDE + 2 + s0;
        float* hrow1 = hb + (ty1 * 4 + 2 * u + 1) * HB_STRIDE + 2 + s0;
        #pragma unroll
        for (int j = 0; j < 4; j++) {
            float lo, hi; unpack2(acc2[u][j], lo, hi);
            hrow0[j] = leaky(lo);
            hrow1[j] = leaky(hi);
        }
    }

    // ================= Phase 2: logits + pools + gates + temporal max ============
    // rows: c0 + ty2*4..+3 (2 row-pairs). cols: s = 2*tx2 + {0,1}.
    const int ty2 = tid >> 5;    // 0..15, warp-uniform
    const int tx2 = tid & 31;

    const float* Wb1 = W1b + (size_t)p * (CH * HID);       // [256][64]
    const float* Wb2 = W2b + (size_t)p * (CH * HID * 3);   // [256][192]
    float* A1s = wb;                     // [64][68]
    float* A2s = wb + 64 * A_STRIDE;     // [192][68]

    for (int c0 = 0; c0 < CH; c0 += 64) {
        __syncthreads();
        // stage A1s[h][cl] = Wb1[c0+cl][h]
        #pragma unroll 2
        for (int i = tid; i < 64 * 64; i += NTHREADS) {
            int cl = i >> 6, h = i & 63;
            A1s[h * A_STRIDE + cl] = Wb1[(c0 + cl) * 64 + h];
        }
        // stage A2s[h*3+k][cl] = Wb2[c0+cl][h][k]
        #pragma unroll 4
        for (int i = tid; i < 64 * 192; i += NTHREADS) {
            int cl = i / 192, kk = i - cl * 192;
            A2s[kk * A_STRIDE + cl] = Wb2[(c0 + cl) * 192 + kk];
        }
        __syncthreads();

        u64 a1c2[2][2], a2c2[2][2];
        #pragma unroll
        for (int u = 0; u < 2; u++)
            #pragma unroll
            for (int j = 0; j < 2; j++) { a1c2[u][j] = 0ull; a2c2[u][j] = 0ull; }

        // branch 1: logits1[c][s] = sum_h W1b[c][h] * h1[h][s]  (K=64)
        {
            const float* ap = A1s + ty2 * 4;
            const float* bp = hb + 2 + 2 * tx2;
            #pragma unroll 4
            for (int kk = 0; kk < 64; kk++) {
                u64 av0, av1;
                lds128p(ap, av0, av1);
                float2 w = *reinterpret_cast<const float2*>(bp);
                u64 bq0 = packrep(w.x), bq1 = packrep(w.y);
                a1c2[0][0] = ffma2(av0, bq0, a1c2[0][0]);
                a1c2[1][0] = ffma2(av1, bq0, a1c2[1][0]);
                a1c2[0][1] = ffma2(av0, bq1, a1c2[0][1]);
                a1c2[1][1] = ffma2(av1, bq1, a1c2[1][1]);
                ap += A_STRIDE;
                bp += HB_STRIDE;
            }
        }

        // branch 2: logits2[c][s] = sum_{h,k} W2b[c][h][k] * h2[h][s+k-1] (K=192)
        {
            const float* ap = A2s + ty2 * 4;
            const float* hp = hb + 64 * HB_STRIDE + 2 * tx2;
            #pragma unroll 2
            for (int hl = 0; hl < 64; hl++) {
                // need data cols 2tx2+1 .. 2tx2+4 (v1..v4)
                float2 w01 = *reinterpret_cast<const float2*>(hp);
                float2 w23 = *reinterpret_cast<const float2*>(hp + 2);
                float  w4  = hp[4];
                u64 bp1 = packrep(w01.y), bp2 = packrep(w23.x);
                u64 bp3 = packrep(w23.y), bp4 = packrep(w4);
                u64 bpv[5];
                bpv[1]=bp1; bpv[2]=bp2; bpv[3]=bp3; bpv[4]=bp4;
                #pragma unroll
                for (int k = 0; k < 3; k++) {
                    u64 av0, av1;
                    lds128p(ap + k * A_STRIDE, av0, av1);
                    #pragma unroll
                    for (int j = 0; j < 2; j++) {
                        a2c2[0][j] = ffma2(av0, bpv[j + k + 1], a2c2[0][j]);
                        a2c2[1][j] = ffma2(av1, bpv[j + k + 1], a2c2[1][j]);
                    }
                }
                ap += 3 * A_STRIDE;
                hp += HB_STRIDE;
            }
        }

        // unpack logits: rows i = 2u + lane half
        float l1[4][2], l2[4][2];
        #pragma unroll
        for (int u = 0; u < 2; u++)
            #pragma unroll
            for (int j = 0; j < 2; j++) {
                float lo, hi;
                unpack2(a1c2[u][j], lo, hi); l1[2*u][j] = lo; l1[2*u+1][j] = hi;
                unpack2(a2c2[u][j], lo, hi); l2[2*u][j] = lo; l2[2*u+1][j] = hi;
            }

        // epilogue: pools + sigmoid gates + combine + max over s
        #pragma unroll
        for (int i = 0; i < 4; i++) {
            const float* xrow = xs + (c0 + ty2 * 4 + i) * XS_STRIDE;
            float m = -INFINITY;
            #pragma unroll
            for (int j = 0; j < 2; j++) {
                int s = 2 * tx2 + j;
                float x0 = xrow[s + 0], x1 = xrow[s + 1], x2 = xrow[s + 2];
                float x3 = xrow[s + 3], x4 = xrow[s + 4];
                float avg3 = (x1 + x2 + x3) * (1.0f / 3.0f);
                float avg5 = (x0 + x1 + x2 + x3 + x4) * 0.2f;
                float mx3 = x2;
                if (s >= 1)  mx3 = fmaxf(mx3, x1);
                if (s <= 62) mx3 = fmaxf(mx3, x3);
                float mx5 = mx3;
                if (s >= 2)  mx5 = fmaxf(mx5, x0);
                if (s <= 61) mx5 = fmaxf(mx5, x4);

                float g1 = sigmoidf_fast(l1[i][j]);
                float g2 = sigmoidf_fast(l2[i][j]);
                float val = (avg3 + mx3) * g1 + (avg5 + mx5) * g2;
                m = fmaxf(m, val);
            }
            #pragma unroll
            for (int off = 16; off > 0; off >>= 1)
                m = fmaxf(m, __shfl_xor_sync(0xffffffffu, m, off));
            if (tx2 == 0)
                out[(size_t)blockIdx.x * CH + c0 + ty2 * 4 + i] = m;
        }
    }
}

extern "C" void kernel_launch(void* const* d_in, const int* in_sizes, int n_in,
                              void* d_out, int out_size)
{
    const float* x   = (const float*)d_in[0];
    const float* W1a = (const float*)d_in[1];
    const float* W1b = (const float*)d_in[2];
    const float* W2a = (const float*)d_in[3];
    const float* W2b = (const float*)d_in[4];
    float* out = (float*)d_out;

    const int smem_bytes = SMEM_FLOATS * (int)sizeof(float);   // 174080
    cudaFuncSetAttribute(mtb_kernel, cudaFuncAttributeMaxDynamicSharedMemorySize,
                         smem_bytes);
    mtb_kernel<<<BB * PARTS, NTHREADS, smem_bytes>>>(x, W1a, W1b, W2a, W2b, out);
}

// round 10
// speedup vs baseline: 1.9874x; 1.7294x over previous
#include <cuda_runtime.h>
#include <math.h>
#include <stdint.h>

#define BB    128
#define SEQ   64
#define CH    256
#define PARTS 16
#define NT    512

#define XS_STR 72
#define H_STR  72
#define XS_OFF 0
#define H_OFF   (256 * XS_STR)             // 18432
#define AS_OFF  (H_OFF + 128 * H_STR)      // 27648 (8192 floats: A frags / partials)
#define PART_OFF (AS_OFF + 8192)           // 35840 (512 floats)
#define SMEM_FL  (PART_OFF + 512)          // 36352 floats = 145408 B

__device__ __forceinline__ uint32_t tf32u(float v) {
    uint32_t u; asm("cvt.rna.tf32.f32 %0, %1;" : "=r"(u) : "f"(v)); return u;
}
__device__ __forceinline__ float leaky(float v) { return (v > 0.f) ? v : 0.01f * v; }
__device__ __forceinline__ float sigmoidf_fast(float v) {
    return 1.0f / (1.0f + __expf(-v));
}
// D[16x8] += A[16x8] * B[8x8]  (tf32 in/out f32)
__device__ __forceinline__ void mma8(float* d, const uint32_t* a,
                                     uint32_t b0, uint32_t b1) {
    asm volatile(
        "mma.sync.aligned.m16n8k8.row.col.f32.tf32.tf32.f32 "
        "{%0,%1,%2,%3}, {%4,%5,%6,%7}, {%8,%9}, {%0,%1,%2,%3};"
        : "+f"(d[0]), "+f"(d[1]), "+f"(d[2]), "+f"(d[3])
        : "r"(a[0]), "r"(a[1]), "r"(a[2]), "r"(a[3]), "r"(b0), "r"(b1));
}

__device__ __forceinline__ float pool_val(int s, float x0, float x1, float x2,
                                          float x3, float x4, float l1, float l2) {
    float avg3 = (x1 + x2 + x3) * (1.0f / 3.0f);
    float avg5 = (x0 + x1 + x2 + x3 + x4) * 0.2f;
    float mx3 = x2;
    if (s >= 1)  mx3 = fmaxf(mx3, x1);
    if (s <= 62) mx3 = fmaxf(mx3, x3);
    float mx5 = mx3;
    if (s >= 2)  mx5 = fmaxf(mx5, x0);
    if (s <= 61) mx5 = fmaxf(mx5, x4);
    return (avg3 + mx3) * sigmoidf_fast(l1) + (avg5 + mx5) * sigmoidf_fast(l2);
}

__global__ void __launch_bounds__(NT, 1)
mtb_mma_kernel(const float* __restrict__ x,
               const float* __restrict__ W1a,
               const float* __restrict__ W1b,
               const float* __restrict__ W2a,
               const float* __restrict__ W2b,
               float* __restrict__ out)
{
    extern __shared__ float smem[];
    float* xs = smem + XS_OFF;          // [256][72], data col = s+2
    float* hb = smem + H_OFF;           // [128][72], rows 0..63 h1, 64..127 h2; data col s+2
    float* As = smem + AS_OFF;          // fragment staging (8192 floats)
    uint4* As4 = reinterpret_cast<uint4*>(As);

    const int tid = threadIdx.x;
    const int wid = tid >> 5;
    const int l   = tid & 31;
    const int b   = blockIdx.x >> 4;
    const int p   = blockIdx.x & 15;

    // ---- zero pads ----
    if (tid < 256) {
        float* row = xs + tid * XS_STR;
        row[0] = 0.f; row[1] = 0.f;
        row[66] = 0.f; row[67] = 0.f; row[68] = 0.f;
        row[69] = 0.f; row[70] = 0.f; row[71] = 0.f;
    }
    if (tid < 128) {
        float* row = hb + tid * H_STR;
        row[0] = 0.f; row[1] = 0.f;
        row[66] = 0.f; row[67] = 0.f; row[68] = 0.f;
        row[69] = 0.f; row[70] = 0.f; row[71] = 0.f;
    }

    // ---- load x slice (exact fp32): xs[c][s+2] = x[((b*64+s)*256+c)*16+p] ----
    {
        const int c  = tid & 255;
        const int sh = tid >> 8;
        const float* xb = x + (size_t)b * (SEQ * CH * PARTS) + p;
        float* xrow = xs + c * XS_STR + 2 + sh * 32;
        #pragma unroll 8
        for (int s = 0; s < 32; s++)
            xrow[s] = xb[(size_t)((sh * 32 + s) * CH + c) * PARTS];
    }

    const float* Wa1 = W1a + (size_t)p * (64 * CH * 3);   // [64][768], kk = c*3+k
    const float* Wa2 = W2a + (size_t)p * (64 * CH * 3);
    const float* Wb1 = W1b + (size_t)p * (CH * 64);       // [256][64]
    const float* Wb2 = W2b + (size_t)p * (CH * 192);      // [256][192], kk = h*3+k

    // ================= Phase 1: D1[128 r][64 s], K=768 (kk = c*3+k) =============
    // warp: ks = wid>>3 (K-split), mrow = (wid>>1)&3 (m32), nh = wid&1 (n32)
    const int ks1   = wid >> 3;
    const int mrow1 = (wid >> 1) & 3;
    const int nh1   = wid & 1;

    float acc[2][4][4];
    #pragma unroll
    for (int i = 0; i < 2; i++)
        #pragma unroll
        for (int j = 0; j < 4; j++)
            #pragma unroll
            for (int t = 0; t < 4; t++) acc[i][j][t] = 0.f;

    for (int g = 0; g < 24; g++) {
        __syncthreads();
        // stage A fragments: 1024 lane-blocks, 2 per thread, STS.128 each
        #pragma unroll
        for (int it = 0; it < 2; it++) {
            int i    = it * NT + tid;
            int ll   = i & 31;
            int msub = (i >> 5) & 7;
            int qq   = i >> 8;
            int r0   = msub * 16 + (ll >> 2);
            int kk0  = g * 32 + qq * 8 + (ll & 3);
            const float* row0 = (r0 < 64) ? (Wa1 + r0 * 768) : (Wa2 + (r0 - 64) * 768);
            const float* row1 = row0 + 8 * 768;
            uint4 v;
            v.x = tf32u(row0[kk0]);
            v.y = tf32u(row1[kk0]);
            v.z = tf32u(row0[kk0 + 4]);
            v.w = tf32u(row1[kk0 + 4]);
            As4[(qq * 8 + msub) * 32 + ll] = v;
        }
        __syncthreads();

        #pragma unroll
        for (int q2 = 0; q2 < 2; q2++) {
            int qq   = ks1 * 2 + q2;
            int kcol = g * 32 + qq * 8 + (l & 3);
            int c0 = kcol / 3,        k0 = kcol - 3 * c0;
            int c1 = (kcol + 4) / 3,  k1 = (kcol + 4) - 3 * c1;
            const float* bp0 = xs + c0 * XS_STR + k0 + 1 + nh1 * 32 + (l >> 2);
            const float* bp1 = xs + c1 * XS_STR + k1 + 1 + nh1 * 32 + (l >> 2);
            uint4 A0 = As4[(qq * 8 + mrow1 * 2)     * 32 + l];
            uint4 A1 = As4[(qq * 8 + mrow1 * 2 + 1) * 32 + l];
            #pragma unroll
            for (int n8 = 0; n8 < 4; n8++) {
                uint32_t b0 = tf32u(bp0[n8 * 8]);
                uint32_t b1 = tf32u(bp1[n8 * 8]);
                mma8(acc[0][n8], reinterpret_cast<uint32_t*>(&A0), b0, b1);
                mma8(acc[1][n8], reinterpret_cast<uint32_t*>(&A1), b0, b1);
            }
        }
    }

    // ---- epilogue 1: merge K-split partials, leaky + tf32 round -> hb ----
    __syncthreads();
    {
        float4* pb = reinterpret_cast<float4*>(As);
        if (ks1 == 1) {
            int base = ((wid - 8) * 32 + l) * 8;
            #pragma unroll
            for (int msub = 0; msub < 2; msub++)
                #pragma unroll
                for (int n8 = 0; n8 < 4; n8++)
                    pb[base + msub * 4 + n8] =
                        make_float4(acc[msub][n8][0], acc[msub][n8][1],
                                    acc[msub][n8][2], acc[msub][n8][3]);
        }
        __syncthreads();
        if (ks1 == 0) {
            int base = (wid * 32 + l) * 8;
            #pragma unroll
            for (int msub = 0; msub < 2; msub++) {
                #pragma unroll
                for (int n8 = 0; n8 < 4; n8++) {
                    float4 t = pb[base + msub * 4 + n8];
                    float d0 = acc[msub][n8][0] + t.x;
                    float d1 = acc[msub][n8][1] + t.y;
                    float d2 = acc[msub][n8][2] + t.z;
                    float d3 = acc[msub][n8][3] + t.w;
                    int r   = mrow1 * 32 + msub * 16 + (l >> 2);
                    int col = nh1 * 32 + n8 * 8 + 2 * (l & 3) + 2;  // +2 pad
                    float* h0 = hb + r * H_STR + col;
                    float* h1 = hb + (r + 8) * H_STR + col;
                    h0[0] = __uint_as_float(tf32u(leaky(d0)));
                    h0[1] = __uint_as_float(tf32u(leaky(d1)));
                    h1[0] = __uint_as_float(tf32u(leaky(d2)));
                    h1[1] = __uint_as_float(tf32u(leaky(d3)));
                }
            }
        }
    }

    // ================= Phase 2: logits1 (K=64) + logits2 (K=192) ===============
    // warp: mrow = wid>>1 (m32 over 256 c-rows), nh = wid&1
    const int mrow2 = wid >> 1;
    const int nh2   = wid & 1;

    float acc1[2][4][4], acc2[2][4][4];
    #pragma unroll
    for (int i = 0; i < 2; i++)
        #pragma unroll
        for (int j = 0; j < 4; j++)
            #pragma unroll
            for (int t = 0; t < 4; t++) { acc1[i][j][t] = 0.f; acc2[i][j][t] = 0.f; }

    // ---- branch 1: A = Wb1 [256][64] ----
    for (int g = 0; g < 2; g++) {
        __syncthreads();
        #pragma unroll
        for (int it = 0; it < 4; it++) {
            int i    = it * NT + tid;
            int ll   = i & 31;
            int msub = (i >> 5) & 15;
            int qq   = i >> 9;
            int r0   = msub * 16 + (ll >> 2);
            int kk0  = g * 32 + qq * 8 + (ll & 3);
            const float* row0 = Wb1 + r0 * 64;
            const float* row1 = row0 + 8 * 64;
            uint4 v;
            v.x = tf32u(row0[kk0]);
            v.y = tf32u(row1[kk0]);
            v.z = tf32u(row0[kk0 + 4]);
            v.w = tf32u(row1[kk0 + 4]);
            As4[(qq * 16 + msub) * 32 + ll] = v;
        }
        __syncthreads();

        #pragma unroll
        for (int qq = 0; qq < 4; qq++) {
            int kcol = g * 32 + qq * 8 + (l & 3);     // = h row of h1
            const float* bp0 = hb + kcol * H_STR + 2 + nh2 * 32 + (l >> 2);
            const float* bp1 = bp0 + 4 * H_STR;
            uint4 A0 = As4[(qq * 16 + mrow2 * 2)     * 32 + l];
            uint4 A1 = As4[(qq * 16 + mrow2 * 2 + 1) * 32 + l];
            #pragma unroll
            for (int n8 = 0; n8 < 4; n8++) {
                uint32_t b0 = __float_as_uint(bp0[n8 * 8]);
                uint32_t b1 = __float_as_uint(bp1[n8 * 8]);
                mma8(acc1[0][n8], reinterpret_cast<uint32_t*>(&A0), b0, b1);
                mma8(acc1[1][n8], reinterpret_cast<uint32_t*>(&A1), b0, b1);
            }
        }
    }

    // ---- branch 2: A = Wb2 [256][192] (kk = h*3+k), B = h2 shifted windows ----
    for (int g = 0; g < 6; g++) {
        __syncthreads();
        #pragma unroll
        for (int it = 0; it < 4; it++) {
            int i    = it * NT + tid;
            int ll   = i & 31;
            int msub = (i >> 5) & 15;
            int qq   = i >> 9;
            int r0   = msub * 16 + (ll >> 2);
            int kk0  = g * 32 + qq * 8 + (ll & 3);
            const float* row0 = Wb2 + r0 * 192;
            const float* row1 = row0 + 8 * 192;
            uint4 v;
            v.x = tf32u(row0[kk0]);
            v.y = tf32u(row1[kk0]);
            v.z = tf32u(row0[kk0 + 4]);
            v.w = tf32u(row1[kk0 + 4]);
            As4[(qq * 16 + msub) * 32 + ll] = v;
        }
        __syncthreads();

        #pragma unroll
        for (int qq = 0; qq < 4; qq++) {
            int kcol = g * 32 + qq * 8 + (l & 3);
            int h0 = kcol / 3,        k0 = kcol - 3 * h0;
            int h1i = (kcol + 4) / 3, k1 = (kcol + 4) - 3 * h1i;
            const float* bp0 = hb + (64 + h0)  * H_STR + k0 + 1 + nh2 * 32 + (l >> 2);
            const float* bp1 = hb + (64 + h1i) * H_STR + k1 + 1 + nh2 * 32 + (l >> 2);
            uint4 A0 = As4[(qq * 16 + mrow2 * 2)     * 32 + l];
            uint4 A1 = As4[(qq * 16 + mrow2 * 2 + 1) * 32 + l];
            #pragma unroll
            for (int n8 = 0; n8 < 4; n8++) {
                uint32_t b0 = __float_as_uint(bp0[n8 * 8]);
                uint32_t b1 = __float_as_uint(bp1[n8 * 8]);
                mma8(acc2[0][n8], reinterpret_cast<uint32_t*>(&A0), b0, b1);
                mma8(acc2[1][n8], reinterpret_cast<uint32_t*>(&A1), b0, b1);
            }
        }
    }

    // ---- epilogue 2: pools + gates + combine + temporal max ----
    float rmax[4] = {-INFINITY, -INFINITY, -INFINITY, -INFINITY};
    #pragma unroll
    for (int msub = 0; msub < 2; msub++) {
        #pragma unroll
        for (int n8 = 0; n8 < 4; n8++) {
            int R0 = mrow2 * 32 + msub * 16 + (l >> 2);
            int s0 = nh2 * 32 + n8 * 8 + 2 * (l & 3);
            #pragma unroll
            for (int rh = 0; rh < 2; rh++) {
                const float* xr = xs + (R0 + rh * 8) * XS_STR + s0;
                float w0 = xr[0], w1 = xr[1], w2 = xr[2];
                float w3 = xr[3], w4 = xr[4], w5 = xr[5];
                float v0 = pool_val(s0, w0, w1, w2, w3, w4,
                                    acc1[msub][n8][rh * 2], acc2[msub][n8][rh * 2]);
                float v1 = pool_val(s0 + 1, w1, w2, w3, w4, w5,
                                    acc1[msub][n8][rh * 2 + 1], acc2[msub][n8][rh * 2 + 1]);
                rmax[msub * 2 + rh] = fmaxf(rmax[msub * 2 + rh], fmaxf(v0, v1));
            }
        }
    }
    // reduce over the 4 lanes sharing the same rows (xor 1, 2)
    #pragma unroll
    for (int off = 1; off <= 2; off <<= 1) {
        #pragma unroll
        for (int i = 0; i < 4; i++)
            rmax[i] = fmaxf(rmax[i], __shfl_xor_sync(0xffffffffu, rmax[i], off));
    }
    {
        int idx = l & 3;
        float v = (idx == 0) ? rmax[0] : (idx == 1) ? rmax[1]
                 : (idx == 2) ? rmax[2] : rmax[3];
        int row = mrow2 * 32 + 16 * (idx >> 1) + 8 * (idx & 1) + (l >> 2);
        smem[PART_OFF + nh2 * 256 + row] = v;
    }
    __syncthreads();
    if (tid < 256)
        out[(size_t)blockIdx.x * CH + tid] =
            fmaxf(smem[PART_OFF + tid], smem[PART_OFF + 256 + tid]);
}

extern "C" void kernel_launch(void* const* d_in, const int* in_sizes, int n_in,
                              void* d_out, int out_size)
{
    const float* x   = (const float*)d_in[0];
    const float* W1a = (const float*)d_in[1];
    const float* W1b = (const float*)d_in[2];
    const float* W2a = (const float*)d_in[3];
    const float* W2b = (const float*)d_in[4];
    float* out = (float*)d_out;

    const int smem_bytes = SMEM_FL * (int)sizeof(float);   // 145408
    cudaFuncSetAttribute(mtb_mma_kernel, cudaFuncAttributeMaxDynamicSharedMemorySize,
                         smem_bytes);
    mtb_mma_kernel<<<BB * PARTS, NT, smem_bytes>>>(x, W1a, W1b, W2a, W2b, out);
}

// round 12
// speedup vs baseline: 3.1065x; 1.5631x over previous
#include <cuda_runtime.h>
#include <math.h>
#include <stdint.h>

#define BB    128
#define SEQ   64
#define CH    256
#define PARTS 16
#define NT    512

#define XST_STR 261                 // 261 % 32 = 5 -> conflict-free quad reads
#define HT_STR  133                 // 133 % 32 = 5
#define A_STR   36                  // 36 % 32 = 4  -> conflict-free A frags

#define XST_OFF 0                               // [68 t][261], data t = s+2
#define HT_OFF  (68 * XST_STR)                  // 17748: [66 t][133], data t = s+1
#define AB_OFF  26528                           // 2 x [256][36] raw weight tiles
#define ABUF_FL 9216
#define PR_OFF  (AB_OFF + ABUF_FL)              // 35744: K-split partials (8192 fl)
#define PART_OFF (AB_OFF + 2*ABUF_FL)           // 44960
#define SMEM_FL  (PART_OFF + 512)               // 45472 fl = 181888 B

__device__ __forceinline__ uint32_t smem_u32(const void* p) {
    uint32_t a;
    asm("{ .reg .u64 t; cvta.to.shared.u64 t, %1; cvt.u32.u64 %0, t; }"
        : "=r"(a) : "l"(p));
    return a;
}
__device__ __forceinline__ uint32_t tf32u(float v) {
    uint32_t u; asm("cvt.rna.tf32.f32 %0, %1;" : "=r"(u) : "f"(v)); return u;
}
__device__ __forceinline__ float leaky(float v) { return (v > 0.f) ? v : 0.01f * v; }
__device__ __forceinline__ float sigmoidf_fast(float v) {
    return 1.0f / (1.0f + __expf(-v));
}
__device__ __forceinline__ void cpa16(uint32_t dst, const void* src) {
    asm volatile("cp.async.cg.shared.global [%0], [%1], 16;" :: "r"(dst), "l"(src));
}
#define CP_COMMIT() asm volatile("cp.async.commit_group;" ::: "memory")
#define CP_WAIT0()  asm volatile("cp.async.wait_group 0;" ::: "memory")
#define CP_WAIT1()  asm volatile("cp.async.wait_group 1;" ::: "memory")

// D[16x8] += A[16x8] * B[8x8]  (tf32 in, f32 out)
__device__ __forceinline__ void mma8(float* d, const uint32_t* a,
                                     uint32_t b0, uint32_t b1) {
    asm volatile(
        "mma.sync.aligned.m16n8k8.row.col.f32.tf32.tf32.f32 "
        "{%0,%1,%2,%3}, {%4,%5,%6,%7}, {%8,%9}, {%0,%1,%2,%3};"
        : "+f"(d[0]), "+f"(d[1]), "+f"(d[2]), "+f"(d[3])
        : "r"(a[0]), "r"(a[1]), "r"(a[2]), "r"(a[3]), "r"(b0), "r"(b1));
}

__device__ __forceinline__ float pool_val(int s, float x0, float x1, float x2,
                                          float x3, float x4, float l1, float l2) {
    float avg3 = (x1 + x2 + x3) * (1.0f / 3.0f);
    float avg5 = (x0 + x1 + x2 + x3 + x4) * 0.2f;
    float mx3 = x2;
    if (s >= 1)  mx3 = fmaxf(mx3, x1);
    if (s <= 62) mx3 = fmaxf(mx3, x3);
    float mx5 = mx3;
    if (s >= 2)  mx5 = fmaxf(mx5, x0);
    if (s <= 61) mx5 = fmaxf(mx5, x4);
    return (avg3 + mx3) * sigmoidf_fast(l1) + (avg5 + mx5) * sigmoidf_fast(l2);
}

__global__ void __launch_bounds__(NT, 1)
mtb_mma2_kernel(const float* __restrict__ x,
                const float* __restrict__ W1a,
                const float* __restrict__ W1b,
                const float* __restrict__ W2a,
                const float* __restrict__ W2b,
                float* __restrict__ out)
{
    extern __shared__ float smem[];
    float* xst = smem + XST_OFF;     // time-major x, exact fp32
    float* ht  = smem + HT_OFF;      // time-major h (tf32-rounded), cols 0..63 h1, 64..127 h2
    const uint32_t ab_addr = smem_u32(smem + AB_OFF);

    const int tid = threadIdx.x;
    const int wid = tid >> 5;
    const int l   = tid & 31;
    const int b   = blockIdx.x >> 4;
    const int p   = blockIdx.x & 15;

    // ---- zero pads ----
    if (tid < 256) {
        xst[0 * XST_STR + tid] = 0.f;
        xst[1 * XST_STR + tid] = 0.f;
        xst[66 * XST_STR + tid] = 0.f;
        xst[67 * XST_STR + tid] = 0.f;
    }
    if (tid < 128) {
        ht[0 * HT_STR + tid] = 0.f;
        ht[65 * HT_STR + tid] = 0.f;
    }

    const float* Wa1 = W1a + (size_t)p * (64 * CH * 3);   // [64][768]
    const float* Wa2 = W2a + (size_t)p * (64 * CH * 3);
    const float* Wb1 = W1b + (size_t)p * (CH * 64);       // [256][64]
    const float* Wb2 = W2b + (size_t)p * (CH * 192);      // [256][192]

    // ---- prefetch phase-1 chunk 0 (overlaps x load) ----
    #pragma unroll
    for (int it = 0; it < 2; it++) {
        int idx = it * NT + tid;
        int row = idx >> 3, col4 = idx & 7;
        const float* src = ((row < 64) ? (Wa1 + row * 768)
                                       : (Wa2 + (row - 64) * 768)) + col4 * 4;
        cpa16(ab_addr + (uint32_t)(row * A_STR + col4 * 4) * 4u, src);
    }
    CP_COMMIT();

    // ---- load x slice (exact fp32, time-major): xst[s+2][c] ----
    {
        const int c  = tid & 255;
        const int sh = tid >> 8;
        const float* xb = x + (size_t)b * (SEQ * CH * PARTS) + p + (size_t)c * PARTS;
        float* xcol = xst + (sh * 32 + 2) * XST_STR + c;
        #pragma unroll 8
        for (int s = 0; s < 32; s++)
            xcol[s * XST_STR] = xb[(size_t)(sh * 32 + s) * (CH * PARTS)];
    }

    // ================= Phase 1: D1[128 r][64 s], K=768 (kk = c*3+k) =============
    const int ks1   = wid >> 3;
    const int mrow1 = (wid >> 1) & 3;
    const int nh1   = wid & 1;

    float acc[2][4][4];
    #pragma unroll
    for (int i = 0; i < 2; i++)
        #pragma unroll
        for (int j = 0; j < 4; j++)
            #pragma unroll
            for (int t = 0; t < 4; t++) acc[i][j][t] = 0.f;

    for (int g = 0; g < 24; g++) {
        const int buf = g & 1;
        if (g + 1 < 24) {
            const int nb = buf ^ 1;
            #pragma unroll
            for (int it = 0; it < 2; it++) {
                int idx = it * NT + tid;
                int row = idx >> 3, col4 = idx & 7;
                const float* src = ((row < 64) ? (Wa1 + row * 768)
                                               : (Wa2 + (row - 64) * 768))
                                   + (g + 1) * 32 + col4 * 4;
                cpa16(ab_addr + (uint32_t)(nb * ABUF_FL + row * A_STR + col4 * 4) * 4u, src);
            }
            CP_COMMIT();
            CP_WAIT1();
        } else {
            CP_WAIT0();
        }
        __syncthreads();

        const float* Ar = smem + AB_OFF + buf * ABUF_FL;
        #pragma unroll
        for (int q2 = 0; q2 < 2; q2++) {
            int qq   = ks1 * 2 + q2;
            int kloc = qq * 8 + (l & 3);
            int kg   = g * 32 + kloc;
            int c0 = kg / 3,       k0 = kg - 3 * c0;
            int c1 = (kg + 4) / 3, k1 = (kg + 4) - 3 * c1;
            const float* bp0 = xst + (nh1 * 32 + (l >> 2) + k0 + 1) * XST_STR + c0;
            const float* bp1 = xst + (nh1 * 32 + (l >> 2) + k1 + 1) * XST_STR + c1;
            uint32_t a[2][4];
            #pragma unroll
            for (int msub = 0; msub < 2; msub++) {
                const float* ap = Ar + (mrow1 * 32 + msub * 16 + (l >> 2)) * A_STR + kloc;
                a[msub][0] = tf32u(ap[0]);
                a[msub][1] = tf32u(ap[8 * A_STR]);
                a[msub][2] = tf32u(ap[4]);
                a[msub][3] = tf32u(ap[8 * A_STR + 4]);
            }
            #pragma unroll
            for (int n8 = 0; n8 < 4; n8++) {
                uint32_t b0 = tf32u(bp0[n8 * 8 * XST_STR]);
                uint32_t b1 = tf32u(bp1[n8 * 8 * XST_STR]);
                mma8(acc[0][n8], a[0], b0, b1);
                mma8(acc[1][n8], a[1], b0, b1);
            }
        }
        __syncthreads();
    }

    // ---- K-split merge: ks1==1 warps publish partials ----
    {
        float4* pb = reinterpret_cast<float4*>(smem + PR_OFF);
        if (ks1 == 1) {
            int base = ((wid - 8) * 32 + l) * 8;
            #pragma unroll
            for (int msub = 0; msub < 2; msub++)
                #pragma unroll
                for (int n8 = 0; n8 < 4; n8++)
                    pb[base + msub * 4 + n8] =
                        make_float4(acc[msub][n8][0], acc[msub][n8][1],
                                    acc[msub][n8][2], acc[msub][n8][3]);
        }
    }
    __syncthreads();

    // ---- prefetch phase-2 tile 0 (Wb1 cols 0..31) into buf 0 ----
    #pragma unroll
    for (int it = 0; it < 4; it++) {
        int idx = it * NT + tid;
        int row = idx >> 3, col4 = idx & 7;
        cpa16(ab_addr + (uint32_t)(row * A_STR + col4 * 4) * 4u,
              Wb1 + row * 64 + col4 * 4);
    }
    CP_COMMIT();

    // ---- epilogue 1 (ks1==0 warps): merge + leaky + tf32 -> ht (time-major) ----
    if (ks1 == 0) {
        const float4* pb = reinterpret_cast<const float4*>(smem + PR_OFF);
        int base = (wid * 32 + l) * 8;
        #pragma unroll
        for (int msub = 0; msub < 2; msub++) {
            #pragma unroll
            for (int n8 = 0; n8 < 4; n8++) {
                float4 t = pb[base + msub * 4 + n8];
                float d0 = acc[msub][n8][0] + t.x;
                float d1 = acc[msub][n8][1] + t.y;
                float d2 = acc[msub][n8][2] + t.z;
                float d3 = acc[msub][n8][3] + t.w;
                int r    = mrow1 * 32 + msub * 16 + (l >> 2);
                int scol = nh1 * 32 + n8 * 8 + 2 * (l & 3);
                float* h0 = ht + (scol + 1) * HT_STR + r;
                float* h1 = ht + (scol + 2) * HT_STR + r;
                h0[0] = __uint_as_float(tf32u(leaky(d0)));
                h1[0] = __uint_as_float(tf32u(leaky(d1)));
                h0[8] = __uint_as_float(tf32u(leaky(d2)));
                h1[8] = __uint_as_float(tf32u(leaky(d3)));
            }
        }
    }
    __syncthreads();

    // ================= Phase 2: logits1 (K=64) + logits2 (K=192) ===============
    const int mrow2 = wid >> 1;     // 0..7 over 256 c-rows
    const int nh2   = wid & 1;

    float acc1[2][4][4], acc2[2][4][4];
    #pragma unroll
    for (int i = 0; i < 2; i++)
        #pragma unroll
        for (int j = 0; j < 4; j++)
            #pragma unroll
            for (int t = 0; t < 4; t++) { acc1[i][j][t] = 0.f; acc2[i][j][t] = 0.f; }

    for (int j = 0; j < 8; j++) {
        const int buf = j & 1;
        if (j + 1 < 8) {
            const int nb = buf ^ 1;
            const int jn = j + 1;
            const float* base = (jn < 2) ? Wb1 : Wb2;
            const int rstr    = (jn < 2) ? 64 : 192;
            const int koff    = (jn < 2) ? jn * 32 : (jn - 2) * 32;
            #pragma unroll
            for (int it = 0; it < 4; it++) {
                int idx = it * NT + tid;
                int row = idx >> 3, col4 = idx & 7;
                cpa16(ab_addr + (uint32_t)(nb * ABUF_FL + row * A_STR + col4 * 4) * 4u,
                      base + row * rstr + koff + col4 * 4);
            }
            CP_COMMIT();
            CP_WAIT1();
        } else {
            CP_WAIT0();
        }
        __syncthreads();

        const float* Ar = smem + AB_OFF + buf * ABUF_FL;
        if (j < 2) {
            // branch 1: B = h1 (ht cols 0..63), k-row = h directly
            #pragma unroll
            for (int qq = 0; qq < 4; qq++) {
                int kloc = qq * 8 + (l & 3);
                int h    = j * 32 + kloc;
                const float* bp = ht + (nh2 * 32 + (l >> 2) + 1) * HT_STR + h;
                uint32_t a[2][4];
                #pragma unroll
                for (int msub = 0; msub < 2; msub++) {
                    const float* ap = Ar + (mrow2 * 32 + msub * 16 + (l >> 2)) * A_STR + kloc;
                    a[msub][0] = tf32u(ap[0]);
                    a[msub][1] = tf32u(ap[8 * A_STR]);
                    a[msub][2] = tf32u(ap[4]);
                    a[msub][3] = tf32u(ap[8 * A_STR + 4]);
                }
                #pragma unroll
                for (int n8 = 0; n8 < 4; n8++) {
                    uint32_t b0 = __float_as_uint(bp[n8 * 8 * HT_STR]);
                    uint32_t b1 = __float_as_uint(bp[n8 * 8 * HT_STR + 4]);
                    mma8(acc1[0][n8], a[0], b0, b1);
                    mma8(acc1[1][n8], a[1], b0, b1);
                }
            }
        } else {
            // branch 2: B = h2 shifted windows (ht cols 64..127), kk = h*3+k
            const int gj = j - 2;
            #pragma unroll
            for (int qq = 0; qq < 4; qq++) {
                int kloc = qq * 8 + (l & 3);
                int kg   = gj * 32 + kloc;
                int h0 = kg / 3,       k0 = kg - 3 * h0;
                int h1 = (kg + 4) / 3, k1 = (kg + 4) - 3 * h1;
                const float* bp0 = ht + (nh2 * 32 + (l >> 2) + k0) * HT_STR + 64 + h0;
                const float* bp1 = ht + (nh2 * 32 + (l >> 2) + k1) * HT_STR + 64 + h1;
                uint32_t a[2][4];
                #pragma unroll
                for (int msub = 0; msub < 2; msub++) {
                    const float* ap = Ar + (mrow2 * 32 + msub * 16 + (l >> 2)) * A_STR + kloc;
                    a[msub][0] = tf32u(ap[0]);
                    a[msub][1] = tf32u(ap[8 * A_STR]);
                    a[msub][2] = tf32u(ap[4]);
                    a[msub][3] = tf32u(ap[8 * A_STR + 4]);
                }
                #pragma unroll
                for (int n8 = 0; n8 < 4; n8++) {
                    uint32_t b0 = __float_as_uint(bp0[n8 * 8 * HT_STR]);
                    uint32_t b1 = __float_as_uint(bp1[n8 * 8 * HT_STR]);
                    mma8(acc2[0][n8], a[0], b0, b1);
                    mma8(acc2[1][n8], a[1], b0, b1);
                }
            }
        }
        __syncthreads();
    }

    // ---- epilogue 2: pools + sigmoid gates + combine + temporal max ----
    float rmax[4] = {-INFINITY, -INFINITY, -INFINITY, -INFINITY};
    #pragma unroll
    for (int msub = 0; msub < 2; msub++) {
        #pragma unroll
        for (int n8 = 0; n8 < 4; n8++) {
            int R0 = mrow2 * 32 + msub * 16 + (l >> 2);
            int s0 = nh2 * 32 + n8 * 8 + 2 * (l & 3);
            #pragma unroll
            for (int rh = 0; rh < 2; rh++) {
                int c = R0 + rh * 8;
                const float* xr = xst + s0 * XST_STR + c;
                float w0 = xr[0],            w1 = xr[XST_STR];
                float w2 = xr[2 * XST_STR],  w3 = xr[3 * XST_STR];
                float w4 = xr[4 * XST_STR],  w5 = xr[5 * XST_STR];
                float v0 = pool_val(s0, w0, w1, w2, w3, w4,
                                    acc1[msub][n8][rh * 2], acc2[msub][n8][rh * 2]);
                float v1 = pool_val(s0 + 1, w1, w2, w3, w4, w5,
                                    acc1[msub][n8][rh * 2 + 1], acc2[msub][n8][rh * 2 + 1]);
                rmax[msub * 2 + rh] = fmaxf(rmax[msub * 2 + rh], fmaxf(v0, v1));
            }
        }
    }
    #pragma unroll
    for (int off = 1; off <= 2; off <<= 1) {
        #pragma unroll
        for (int i = 0; i < 4; i++)
            rmax[i] = fmaxf(rmax[i], __shfl_xor_sync(0xffffffffu, rmax[i], off));
    }
    {
        int idx = l & 3;
        float v = (idx == 0) ? rmax[0] : (idx == 1) ? rmax[1]
                 : (idx == 2) ? rmax[2] : rmax[3];
        int row = mrow2 * 32 + 16 * (idx >> 1) + 8 * (idx & 1) + (l >> 2);
        smem[PART_OFF + nh2 * 256 + row] = v;
    }
    __syncthreads();
    if (tid < 256)
        out[(size_t)blockIdx.x * CH + tid] =
            fmaxf(smem[PART_OFF + tid], smem[PART_OFF + 256 + tid]);
}

extern "C" void kernel_launch(void* const* d_in, const int* in_sizes, int n_in,
                              void* d_out, int out_size)
{
    const float* x   = (const float*)d_in[0];
    const float* W1a = (const float*)d_in[1];
    const float* W1b = (const float*)d_in[2];
    const float* W2a = (const float*)d_in[3];
    const float* W2b = (const float*)d_in[4];
    float* out = (float*)d_out;

    const int smem_bytes = SMEM_FL * (int)sizeof(float);   // 181888
    cudaFuncSetAttribute(mtb_mma2_kernel, cudaFuncAttributeMaxDynamicSharedMemorySize,
                         smem_bytes);
    mtb_mma2_kernel<<<BB * PARTS, NT, smem_bytes>>>(x, W1a, W1b, W2a, W2b, out);
}